// round 13
// baseline (speedup 1.0000x reference)
#include <cuda_runtime.h>
#include <cuda_fp16.h>
#include <math.h>

#define NN 50000        // num nodes
#define DD 128          // embedding dim (= hidden dim)
#define BB 4            // num bases
#define EE 320000       // num edges
#define BH 512          // BB * DD

// ---------------- static scratch ----------------
__device__ float  g_x[NN * DD];          // node features, 25.6 MB
__device__ __half g_hb_h[NN * BH];       // per-base projections (fp16), 51.2 MB
__device__ float  g_agg[NN * DD];        // scatter accumulator, 25.6 MB
__device__ __half g_Wt[2 * BB * DD * DD];// transposed bases [layer][b][n][k] fp16
__device__ int    g_deg[NN];
__device__ int    g_off[NN + 1];
__device__ int    g_cur[NN];
__device__ int    g_ssrc[EE];            // src, dst-sorted
__device__ int    g_sdst[EE];            // dst, dst-sorted
__device__ int    g_set[EE];             // edge type, dst-sorted
__device__ double g_acc[3];              // loss_pos, loss_neg, auc_count

// ---------------- degree ----------------
__global__ void k_zero_deg() {
    int i = blockIdx.x * blockDim.x + threadIdx.x;
    if (i < NN) g_deg[i] = 0;
}
__global__ void k_count_deg(const int* __restrict__ dst) {
    int e = blockIdx.x * blockDim.x + threadIdx.x;
    if (e < EE) atomicAdd(&g_deg[dst[e]], 1);
}

// ---------------- single-block prefix scan ----------------
#define SCAN_T 1024
#define SCAN_CH 49
__global__ __launch_bounds__(SCAN_T) void k_scan() {
    __shared__ int sh[SCAN_T];
    int t = threadIdx.x;
    int base = t * SCAN_CH;
    int loc[SCAN_CH];
    int s = 0;
#pragma unroll
    for (int j = 0; j < SCAN_CH; j++) {
        int idx = base + j;
        loc[j] = s;
        if (idx < NN) s += g_deg[idx];
    }
    sh[t] = s;
    __syncthreads();
    for (int off = 1; off < SCAN_T; off <<= 1) {
        int v = (t >= off) ? sh[t - off] : 0;
        __syncthreads();
        sh[t] += v;
        __syncthreads();
    }
    int pre = (t == 0) ? 0 : sh[t - 1];
#pragma unroll
    for (int j = 0; j < SCAN_CH; j++) {
        int idx = base + j;
        if (idx < NN) {
            int o = pre + loc[j];
            g_off[idx] = o;
            g_cur[idx] = o;
        }
    }
    if (t == SCAN_T - 1) g_off[NN] = sh[t];
}

// ---------------- bucket edges by dst ----------------
__global__ void k_fill(const int* __restrict__ src, const int* __restrict__ dst,
                       const int* __restrict__ et) {
    int e = blockIdx.x * blockDim.x + threadIdx.x;
    if (e < EE) {
        int d = dst[e];
        int pos = atomicAdd(&g_cur[d], 1);
        g_ssrc[pos] = src[e];
        g_sdst[pos] = d;
        g_set[pos]  = et[e];
    }
}

// ---------------- transpose bases -> g_Wt[layer][b][n][k] fp16 ----------------
__global__ void k_wt(const float* __restrict__ bases, int layer) {
    int i = blockIdx.x * blockDim.x + threadIdx.x;
    if (i < BB * DD * DD) {
        int b = i >> 14, k = (i >> 7) & 127, n = i & 127;
        g_Wt[((layer * BB + b) * DD + n) * DD + k] = __float2half(bases[i]);
    }
}

// ---------------- x0 = relu(emb + bias), zero agg (float4) ----------------
__global__ void k_x0(const float* __restrict__ emb, const float* __restrict__ eb) {
    int i = blockIdx.x * blockDim.x + threadIdx.x;
    if (i < NN * DD / 4) {
        float4 v = *(const float4*)&emb[i * 4];
        float4 bsv = *(const float4*)&eb[(i & 31) * 4];
        v.x = fmaxf(v.x + bsv.x, 0.f);
        v.y = fmaxf(v.y + bsv.y, 0.f);
        v.z = fmaxf(v.z + bsv.z, 0.f);
        v.w = fmaxf(v.w + bsv.w, 0.f);
        *(float4*)&g_x[i * 4] = v;
        *(float4*)&g_agg[i * 4] = make_float4(0.f, 0.f, 0.f, 0.f);
    }
}

// ---------------- f16 mma helper ----------------
__device__ __forceinline__ void mma_f16(float c[4], const unsigned a[4], const unsigned b[2]) {
    asm volatile(
        "mma.sync.aligned.m16n8k16.row.col.f32.f16.f16.f32 "
        "{%0,%1,%2,%3}, {%4,%5,%6,%7}, {%8,%9}, {%0,%1,%2,%3};\n"
        : "+f"(c[0]), "+f"(c[1]), "+f"(c[2]), "+f"(c[3])
        : "r"(a[0]), "r"(a[1]), "r"(a[2]), "r"(a[3]), "r"(b[0]), "r"(b[1]));
}

// ---------------- fp16 GEMM: g_hb_h[N,512] = g_x[N,128] @ W[b] ----------------
__global__ __launch_bounds__(256, 2) void k_gemm_mma(int layer) {
    __shared__ unsigned Xs[128][20];
    __shared__ unsigned Wst[128][20];

    const int b  = blockIdx.x;
    const int bm = blockIdx.y * 128;
    const int tid = threadIdx.x;
    const int lane = tid & 31;
    const int wid = tid >> 5;
    const int wm = wid & 3;
    const int wn = wid >> 2;
    const int gid = lane >> 2;
    const int tig = lane & 3;

    const __half* Wtb = &g_Wt[(layer * BB + b) * DD * DD];

    float c[2][8][4];
#pragma unroll
    for (int mt = 0; mt < 2; mt++)
#pragma unroll
        for (int nt = 0; nt < 8; nt++)
#pragma unroll
            for (int i = 0; i < 4; i++) c[mt][nt][i] = 0.f;

#pragma unroll
    for (int kc = 0; kc < 4; kc++) {
#pragma unroll
        for (int it = 0; it < 4; it++) {
            int idx = it * 256 + tid;
            int r = idx >> 3, c4 = idx & 7;
            float4 a = make_float4(0.f, 0.f, 0.f, 0.f);
            int grow = bm + r;
            if (grow < NN) a = *(const float4*)&g_x[grow * DD + kc * 32 + c4 * 4];
            __half2 h0 = __floats2half2_rn(a.x, a.y);
            __half2 h1 = __floats2half2_rn(a.z, a.w);
            Xs[r][c4 * 2 + 0] = *(const unsigned*)&h0;
            Xs[r][c4 * 2 + 1] = *(const unsigned*)&h1;
        }
#pragma unroll
        for (int it = 0; it < 2; it++) {
            int idx = it * 256 + tid;
            int n = idx >> 2, j4 = idx & 3;
            uint4 u = *(const uint4*)&Wtb[n * DD + kc * 32 + j4 * 8];
            *(uint4*)&Wst[n][j4 * 4] = u;
        }
        __syncthreads();

#pragma unroll
        for (int ks = 0; ks < 2; ks++) {
            const int o0 = ks * 8 + tig;
            const int o1 = o0 + 4;
            unsigned a[2][4], bf[8][2];
#pragma unroll
            for (int mt = 0; mt < 2; mt++) {
                int mr = wm * 32 + mt * 16 + gid;
                a[mt][0] = Xs[mr][o0];
                a[mt][1] = Xs[mr + 8][o0];
                a[mt][2] = Xs[mr][o1];
                a[mt][3] = Xs[mr + 8][o1];
            }
#pragma unroll
            for (int nt = 0; nt < 8; nt++) {
                int nc = wn * 64 + nt * 8 + gid;
                bf[nt][0] = Wst[nc][o0];
                bf[nt][1] = Wst[nc][o1];
            }
#pragma unroll
            for (int mt = 0; mt < 2; mt++)
#pragma unroll
                for (int nt = 0; nt < 8; nt++)
                    mma_f16(c[mt][nt], a[mt], bf[nt]);
        }
        __syncthreads();
    }

#pragma unroll
    for (int mt = 0; mt < 2; mt++) {
        int row0 = bm + wm * 32 + mt * 16 + gid;
        int row1 = row0 + 8;
#pragma unroll
        for (int nt = 0; nt < 8; nt++) {
            int col = b * 128 + wn * 64 + nt * 8 + 2 * tig;
            if (row0 < NN)
                *(__half2*)&g_hb_h[row0 * BH + col] = __floats2half2_rn(c[mt][nt][0], c[mt][nt][1]);
            if (row1 < NN)
                *(__half2*)&g_hb_h[row1 * BH + col] = __floats2half2_rn(c[mt][nt][2], c[mt][nt][3]);
        }
    }
}

// ---------------- sorted-run scatter, hoisted gathers: warp per 8 dst-sorted edges ----------------
__device__ __forceinline__ void red4(float* p, float4 v) {
    asm volatile("red.global.add.v4.f32 [%0], {%1,%2,%3,%4};"
                 :: "l"(p), "f"(v.x), "f"(v.y), "f"(v.z), "f"(v.w) : "memory");
}

__global__ __launch_bounds__(256) void k_scatter(const float* __restrict__ comp) {
    int w = (blockIdx.x * blockDim.x + threadIdx.x) >> 5;
    int lane = threadIdx.x & 31;
    int base = w * 8;
    if (base >= EE) return;     // EE % 8 == 0

    int4 s03 = *(const int4*)&g_ssrc[base];
    int4 s47 = *(const int4*)&g_ssrc[base + 4];
    int4 d03 = *(const int4*)&g_sdst[base];
    int4 d47 = *(const int4*)&g_sdst[base + 4];
    int4 t03 = *(const int4*)&g_set[base];
    int4 t47 = *(const int4*)&g_set[base + 4];
    int s[8] = {s03.x, s03.y, s03.z, s03.w, s47.x, s47.y, s47.z, s47.w};
    int d[8] = {d03.x, d03.y, d03.z, d03.w, d47.x, d47.y, d47.z, d47.w};
    int t[8] = {t03.x, t03.y, t03.z, t03.w, t47.x, t47.y, t47.z, t47.w};

    // ---- phase 1: issue ALL gather loads (no stores/atomics between -> full MLP) ----
    uint2 raw[8][4];
#pragma unroll
    for (int j = 0; j < 8; j++) {
        const uint2* hb = (const uint2*)&g_hb_h[(size_t)s[j] * BH];
        raw[j][0] = __ldg(&hb[lane]);
        raw[j][1] = __ldg(&hb[32 + lane]);
        raw[j][2] = __ldg(&hb[64 + lane]);
        raw[j][3] = __ldg(&hb[96 + lane]);
    }

    // ---- phase 2: convert + combine with comp coefficients ----
    float4 m[8];
#pragma unroll
    for (int j = 0; j < 8; j++) {
        float4 cf = __ldg((const float4*)&comp[t[j] * BB]);
        float2 a0 = __half22float2(*(const __half2*)&raw[j][0].x);
        float2 b0 = __half22float2(*(const __half2*)&raw[j][0].y);
        float2 a1 = __half22float2(*(const __half2*)&raw[j][1].x);
        float2 b1 = __half22float2(*(const __half2*)&raw[j][1].y);
        float2 a2 = __half22float2(*(const __half2*)&raw[j][2].x);
        float2 b2 = __half22float2(*(const __half2*)&raw[j][2].y);
        float2 a3 = __half22float2(*(const __half2*)&raw[j][3].x);
        float2 b3 = __half22float2(*(const __half2*)&raw[j][3].y);
        m[j].x = cf.x * a0.x + cf.y * a1.x + cf.z * a2.x + cf.w * a3.x;
        m[j].y = cf.x * a0.y + cf.y * a1.y + cf.z * a2.y + cf.w * a3.y;
        m[j].z = cf.x * b0.x + cf.y * b1.x + cf.z * b2.x + cf.w * b3.x;
        m[j].w = cf.x * b0.y + cf.y * b1.y + cf.z * b2.y + cf.w * b3.y;
    }

    // ---- phase 3: merge equal-dst runs, red only at boundaries ----
    float4 acc = m[0];
#pragma unroll
    for (int j = 1; j < 8; j++) {
        if (d[j] == d[j - 1]) {
            acc.x += m[j].x; acc.y += m[j].y; acc.z += m[j].z; acc.w += m[j].w;
        } else {
            red4(&g_agg[d[j - 1] * DD + lane * 4], acc);
            acc = m[j];
        }
    }
    red4(&g_agg[d[7] * DD + lane * 4], acc);
}

// ---------------- x = [relu](agg / deg + bias), reset agg (float4) ----------------
__global__ void k_finish(const float* __restrict__ bias, int do_relu) {
    int i = blockIdx.x * blockDim.x + threadIdx.x;
    if (i < NN * DD / 4) {
        int n = i >> 5;
        float inv = 1.0f / fmaxf((float)g_deg[n], 1.0f);
        float4 v = *(const float4*)&g_agg[i * 4];
        float4 bsv = *(const float4*)&bias[(i & 31) * 4];
        v.x = v.x * inv + bsv.x;
        v.y = v.y * inv + bsv.y;
        v.z = v.z * inv + bsv.z;
        v.w = v.w * inv + bsv.w;
        if (do_relu) {
            v.x = fmaxf(v.x, 0.f); v.y = fmaxf(v.y, 0.f);
            v.z = fmaxf(v.z, 0.f); v.w = fmaxf(v.w, 0.f);
        }
        *(float4*)&g_x[i * 4] = v;
        *(float4*)&g_agg[i * 4] = make_float4(0.f, 0.f, 0.f, 0.f);
    }
}

// ---------------- decode ----------------
__global__ void k_zero_acc() {
    int i = threadIdx.x;
    if (i < 3) g_acc[i] = 0.0;
}

__device__ __forceinline__ float softplusf(float x) {
    return fmaxf(x, 0.f) + log1pf(expf(-fabsf(x)));
}

__global__ __launch_bounds__(256) void k_decode(const int* __restrict__ hh,
                                                const int* __restrict__ tt,
                                                const int* __restrict__ et,
                                                const int* __restrict__ ng,
                                                const float* __restrict__ rel,
                                                float* __restrict__ out) {
    __shared__ float s_lp[8], s_ln[8], s_au[8];
    int w = (blockIdx.x * blockDim.x + threadIdx.x) >> 5;
    int lane = threadIdx.x & 31;
    int wid = threadIdx.x >> 5;
    float lp = 0.f, ln = 0.f, au = 0.f;
    if (w < EE) {
        int a = hh[w], b = tt[w], c = ng[w], r = et[w];
        float4 xh = *(const float4*)&g_x[a * DD + lane * 4];
        float4 xt = *(const float4*)&g_x[b * DD + lane * 4];
        float4 xn = *(const float4*)&g_x[c * DD + lane * 4];
        float4 re = *(const float4*)&rel[r * DD + lane * 4];
        float hx = xh.x * re.x, hy = xh.y * re.y, hz = xh.z * re.z, hw = xh.w * re.w;
        float p = hx * xt.x + hy * xt.y + hz * xt.z + hw * xt.w;
        float q = hx * xn.x + hy * xn.y + hz * xn.z + hw * xn.w;
#pragma unroll
        for (int o = 16; o; o >>= 1) {
            p += __shfl_xor_sync(0xFFFFFFFFu, p, o);
            q += __shfl_xor_sync(0xFFFFFFFFu, q, o);
        }
        if (lane == 0) {
            out[w] = p;
            lp = softplusf(-p);
            ln = softplusf(q);
            au = (p > q) ? 1.f : 0.f;
        }
    }
    if (lane == 0) { s_lp[wid] = lp; s_ln[wid] = ln; s_au[wid] = au; }
    __syncthreads();
    if (threadIdx.x == 0) {
        double A = 0, Bd = 0, C = 0;
#pragma unroll
        for (int k = 0; k < 8; k++) { A += s_lp[k]; Bd += s_ln[k]; C += s_au[k]; }
        atomicAdd(&g_acc[0], A);
        atomicAdd(&g_acc[1], Bd);
        atomicAdd(&g_acc[2], C);
    }
}

__global__ void k_final(float* __restrict__ out, int out_size) {
    if (blockIdx.x == 0 && threadIdx.x == 0) {
        double inv = 1.0 / (double)EE;
        if (out_size >= EE + 1) out[EE] = (float)(0.5 * (g_acc[0] + g_acc[1]) * inv);
        if (out_size >= EE + 2) out[EE + 1] = (float)(g_acc[2] * inv);
    }
}

// ---------------- launch ----------------
extern "C" void kernel_launch(void* const* d_in, const int* in_sizes, int n_in,
                              void* d_out, int out_size) {
    const float* emb    = (const float*)d_in[0];
    const float* ebias  = (const float*)d_in[1];
    const float* bases1 = (const float*)d_in[2];
    const float* comp1  = (const float*)d_in[3];
    const float* bias1  = (const float*)d_in[4];
    const float* bases2 = (const float*)d_in[5];
    const float* comp2  = (const float*)d_in[6];
    const float* bias2  = (const float*)d_in[7];
    const float* rel    = (const float*)d_in[8];
    const int*   eidx   = (const int*)d_in[9];
    const int*   etype  = (const int*)d_in[10];
    const int*   negt   = (const int*)d_in[11];
    const int* src = eidx;
    const int* dst = eidx + EE;
    float* out = (float*)d_out;

    // CSR build (dst-sorted edge arrays) + W transposes + x0
    k_zero_deg<<<(NN + 255) / 256, 256>>>();
    k_count_deg<<<(EE + 255) / 256, 256>>>(dst);
    k_scan<<<1, SCAN_T>>>();
    k_fill<<<(EE + 255) / 256, 256>>>(src, dst, etype);
    k_wt<<<(BB * DD * DD + 255) / 256, 256>>>(bases1, 0);
    k_wt<<<(BB * DD * DD + 255) / 256, 256>>>(bases2, 1);
    k_x0<<<(NN * DD / 4 + 255) / 256, 256>>>(emb, ebias);

    dim3 ggrid(BB, (NN + 127) / 128);   // (4, 391)
    int sc_blocks = EE / 8 / 8;         // warp = 8 edges, 8 warps/block -> 5000 blocks

    // ---- layer 1 ----
    k_gemm_mma<<<ggrid, 256>>>(0);
    k_scatter<<<sc_blocks, 256>>>(comp1);
    k_finish<<<(NN * DD / 4 + 255) / 256, 256>>>(bias1, 1);

    // ---- layer 2 ----
    k_gemm_mma<<<ggrid, 256>>>(1);
    k_scatter<<<sc_blocks, 256>>>(comp2);
    k_finish<<<(NN * DD / 4 + 255) / 256, 256>>>(bias2, 0);

    // ---- decode ----
    k_zero_acc<<<1, 32>>>();
    k_decode<<<EE / 8, 256>>>(src, dst, etype, negt, rel, out);
    k_final<<<1, 32>>>(out, out_size);
}

// round 15
// speedup vs baseline: 1.0197x; 1.0197x over previous
#include <cuda_runtime.h>
#include <cuda_fp16.h>
#include <math.h>

#define NN 50000        // num nodes
#define DD 128          // embedding dim (= hidden dim)
#define BB 4            // num bases
#define EE 320000       // num edges
#define BH 512          // BB * DD

// ---------------- static scratch ----------------
__device__ float  g_x[NN * DD];          // node features, 25.6 MB
__device__ __half g_hb_h[NN * BH];       // per-base projections (fp16), 51.2 MB
__device__ float  g_agg[NN * DD];        // scatter accumulator, 25.6 MB
__device__ __half g_Wt[2 * BB * DD * DD];// transposed bases [layer][b][n][k] fp16
__device__ int    g_deg[NN];
__device__ int    g_off[NN + 1];
__device__ int    g_cur[NN];
__device__ int    g_ssrc[EE];            // src, dst-sorted
__device__ int    g_sdst[EE];            // dst, dst-sorted
__device__ int    g_set[EE];             // edge type, dst-sorted
__device__ double g_acc[3];              // loss_pos, loss_neg, auc_count

// ---------------- degree ----------------
__global__ void k_zero_deg() {
    int i = blockIdx.x * blockDim.x + threadIdx.x;
    if (i < NN) g_deg[i] = 0;
}
__global__ void k_count_deg(const int* __restrict__ dst) {
    int e = blockIdx.x * blockDim.x + threadIdx.x;
    if (e < EE) atomicAdd(&g_deg[dst[e]], 1);
}

// ---------------- single-block prefix scan ----------------
#define SCAN_T 1024
#define SCAN_CH 49
__global__ __launch_bounds__(SCAN_T) void k_scan() {
    __shared__ int sh[SCAN_T];
    int t = threadIdx.x;
    int base = t * SCAN_CH;
    int loc[SCAN_CH];
    int s = 0;
#pragma unroll
    for (int j = 0; j < SCAN_CH; j++) {
        int idx = base + j;
        loc[j] = s;
        if (idx < NN) s += g_deg[idx];
    }
    sh[t] = s;
    __syncthreads();
    for (int off = 1; off < SCAN_T; off <<= 1) {
        int v = (t >= off) ? sh[t - off] : 0;
        __syncthreads();
        sh[t] += v;
        __syncthreads();
    }
    int pre = (t == 0) ? 0 : sh[t - 1];
#pragma unroll
    for (int j = 0; j < SCAN_CH; j++) {
        int idx = base + j;
        if (idx < NN) {
            int o = pre + loc[j];
            g_off[idx] = o;
            g_cur[idx] = o;
        }
    }
    if (t == SCAN_T - 1) g_off[NN] = sh[t];
}

// ---------------- bucket edges by dst ----------------
__global__ void k_fill(const int* __restrict__ src, const int* __restrict__ dst,
                       const int* __restrict__ et) {
    int e = blockIdx.x * blockDim.x + threadIdx.x;
    if (e < EE) {
        int d = dst[e];
        int pos = atomicAdd(&g_cur[d], 1);
        g_ssrc[pos] = src[e];
        g_sdst[pos] = d;
        g_set[pos]  = et[e];
    }
}

// ---------------- transpose bases -> g_Wt[layer][b][n][k] fp16 ----------------
__global__ void k_wt(const float* __restrict__ bases, int layer) {
    int i = blockIdx.x * blockDim.x + threadIdx.x;
    if (i < BB * DD * DD) {
        int b = i >> 14, k = (i >> 7) & 127, n = i & 127;
        g_Wt[((layer * BB + b) * DD + n) * DD + k] = __float2half(bases[i]);
    }
}

// ---------------- x0 = relu(emb + bias), zero agg (float4) ----------------
__global__ void k_x0(const float* __restrict__ emb, const float* __restrict__ eb) {
    int i = blockIdx.x * blockDim.x + threadIdx.x;
    if (i < NN * DD / 4) {
        float4 v = *(const float4*)&emb[i * 4];
        float4 bsv = *(const float4*)&eb[(i & 31) * 4];
        v.x = fmaxf(v.x + bsv.x, 0.f);
        v.y = fmaxf(v.y + bsv.y, 0.f);
        v.z = fmaxf(v.z + bsv.z, 0.f);
        v.w = fmaxf(v.w + bsv.w, 0.f);
        *(float4*)&g_x[i * 4] = v;
        *(float4*)&g_agg[i * 4] = make_float4(0.f, 0.f, 0.f, 0.f);
    }
}

// ---------------- f16 mma helper ----------------
__device__ __forceinline__ void mma_f16(float c[4], const unsigned a[4], const unsigned b[2]) {
    asm volatile(
        "mma.sync.aligned.m16n8k16.row.col.f32.f16.f16.f32 "
        "{%0,%1,%2,%3}, {%4,%5,%6,%7}, {%8,%9}, {%0,%1,%2,%3};\n"
        : "+f"(c[0]), "+f"(c[1]), "+f"(c[2]), "+f"(c[3])
        : "r"(a[0]), "r"(a[1]), "r"(a[2]), "r"(a[3]), "r"(b[0]), "r"(b[1]));
}

// ---------------- fp16 GEMM: g_hb_h[N,512] = g_x[N,128] @ W[b] ----------------
__global__ __launch_bounds__(256, 2) void k_gemm_mma(int layer) {
    __shared__ unsigned Xs[128][20];
    __shared__ unsigned Wst[128][20];

    const int b  = blockIdx.x;
    const int bm = blockIdx.y * 128;
    const int tid = threadIdx.x;
    const int lane = tid & 31;
    const int wid = tid >> 5;
    const int wm = wid & 3;
    const int wn = wid >> 2;
    const int gid = lane >> 2;
    const int tig = lane & 3;

    const __half* Wtb = &g_Wt[(layer * BB + b) * DD * DD];

    float c[2][8][4];
#pragma unroll
    for (int mt = 0; mt < 2; mt++)
#pragma unroll
        for (int nt = 0; nt < 8; nt++)
#pragma unroll
            for (int i = 0; i < 4; i++) c[mt][nt][i] = 0.f;

#pragma unroll
    for (int kc = 0; kc < 4; kc++) {
#pragma unroll
        for (int it = 0; it < 4; it++) {
            int idx = it * 256 + tid;
            int r = idx >> 3, c4 = idx & 7;
            float4 a = make_float4(0.f, 0.f, 0.f, 0.f);
            int grow = bm + r;
            if (grow < NN) a = *(const float4*)&g_x[grow * DD + kc * 32 + c4 * 4];
            __half2 h0 = __floats2half2_rn(a.x, a.y);
            __half2 h1 = __floats2half2_rn(a.z, a.w);
            Xs[r][c4 * 2 + 0] = *(const unsigned*)&h0;
            Xs[r][c4 * 2 + 1] = *(const unsigned*)&h1;
        }
#pragma unroll
        for (int it = 0; it < 2; it++) {
            int idx = it * 256 + tid;
            int n = idx >> 2, j4 = idx & 3;
            uint4 u = *(const uint4*)&Wtb[n * DD + kc * 32 + j4 * 8];
            *(uint4*)&Wst[n][j4 * 4] = u;
        }
        __syncthreads();

#pragma unroll
        for (int ks = 0; ks < 2; ks++) {
            const int o0 = ks * 8 + tig;
            const int o1 = o0 + 4;
            unsigned a[2][4], bf[8][2];
#pragma unroll
            for (int mt = 0; mt < 2; mt++) {
                int mr = wm * 32 + mt * 16 + gid;
                a[mt][0] = Xs[mr][o0];
                a[mt][1] = Xs[mr + 8][o0];
                a[mt][2] = Xs[mr][o1];
                a[mt][3] = Xs[mr + 8][o1];
            }
#pragma unroll
            for (int nt = 0; nt < 8; nt++) {
                int nc = wn * 64 + nt * 8 + gid;
                bf[nt][0] = Wst[nc][o0];
                bf[nt][1] = Wst[nc][o1];
            }
#pragma unroll
            for (int mt = 0; mt < 2; mt++)
#pragma unroll
                for (int nt = 0; nt < 8; nt++)
                    mma_f16(c[mt][nt], a[mt], bf[nt]);
        }
        __syncthreads();
    }

#pragma unroll
    for (int mt = 0; mt < 2; mt++) {
        int row0 = bm + wm * 32 + mt * 16 + gid;
        int row1 = row0 + 8;
#pragma unroll
        for (int nt = 0; nt < 8; nt++) {
            int col = b * 128 + wn * 64 + nt * 8 + 2 * tig;
            if (row0 < NN)
                *(__half2*)&g_hb_h[row0 * BH + col] = __floats2half2_rn(c[mt][nt][0], c[mt][nt][1]);
            if (row1 < NN)
                *(__half2*)&g_hb_h[row1 * BH + col] = __floats2half2_rn(c[mt][nt][2], c[mt][nt][3]);
        }
    }
}

// ---------------- sorted-run scatter, 4-edge windows (reg-pressure safe) ----------------
__device__ __forceinline__ void red4(float* p, float4 v) {
    asm volatile("red.global.add.v4.f32 [%0], {%1,%2,%3,%4};"
                 :: "l"(p), "f"(v.x), "f"(v.y), "f"(v.z), "f"(v.w) : "memory");
}

__global__ __launch_bounds__(256) void k_scatter(const float* __restrict__ comp) {
    int w = (blockIdx.x * blockDim.x + threadIdx.x) >> 5;   // window of 4 edges
    int lane = threadIdx.x & 31;
    int base = w * 4;
    if (base >= EE) return;     // EE % 4 == 0

    int4 s4 = *(const int4*)&g_ssrc[base];
    int4 d4 = *(const int4*)&g_sdst[base];
    int4 t4 = *(const int4*)&g_set[base];
    int s[4] = {s4.x, s4.y, s4.z, s4.w};
    int d[4] = {d4.x, d4.y, d4.z, d4.w};
    int t[4] = {t4.x, t4.y, t4.z, t4.w};

    // phase 1: all gather loads issued back-to-back (full MLP, no clobbers between)
    uint2 raw[4][4];
#pragma unroll
    for (int j = 0; j < 4; j++) {
        const uint2* hb = (const uint2*)&g_hb_h[(size_t)s[j] * BH];
        raw[j][0] = __ldg(&hb[lane]);
        raw[j][1] = __ldg(&hb[32 + lane]);
        raw[j][2] = __ldg(&hb[64 + lane]);
        raw[j][3] = __ldg(&hb[96 + lane]);
    }

    // phase 2: convert + combine
    float4 m[4];
#pragma unroll
    for (int j = 0; j < 4; j++) {
        float4 cf = __ldg((const float4*)&comp[t[j] * BB]);
        float2 a0 = __half22float2(*(const __half2*)&raw[j][0].x);
        float2 b0 = __half22float2(*(const __half2*)&raw[j][0].y);
        float2 a1 = __half22float2(*(const __half2*)&raw[j][1].x);
        float2 b1 = __half22float2(*(const __half2*)&raw[j][1].y);
        float2 a2 = __half22float2(*(const __half2*)&raw[j][2].x);
        float2 b2 = __half22float2(*(const __half2*)&raw[j][2].y);
        float2 a3 = __half22float2(*(const __half2*)&raw[j][3].x);
        float2 b3 = __half22float2(*(const __half2*)&raw[j][3].y);
        m[j].x = cf.x * a0.x + cf.y * a1.x + cf.z * a2.x + cf.w * a3.x;
        m[j].y = cf.x * a0.y + cf.y * a1.y + cf.z * a2.y + cf.w * a3.y;
        m[j].z = cf.x * b0.x + cf.y * b1.x + cf.z * b2.x + cf.w * b3.x;
        m[j].w = cf.x * b0.y + cf.y * b1.y + cf.z * b2.y + cf.w * b3.y;
    }

    // phase 3: merge equal-dst runs, red only at boundaries
    float4 acc = m[0];
#pragma unroll
    for (int j = 1; j < 4; j++) {
        if (d[j] == d[j - 1]) {
            acc.x += m[j].x; acc.y += m[j].y; acc.z += m[j].z; acc.w += m[j].w;
        } else {
            red4(&g_agg[d[j - 1] * DD + lane * 4], acc);
            acc = m[j];
        }
    }
    red4(&g_agg[d[3] * DD + lane * 4], acc);
}

// ---------------- x = [relu](agg / deg + bias), reset agg (float4) ----------------
__global__ void k_finish(const float* __restrict__ bias, int do_relu) {
    int i = blockIdx.x * blockDim.x + threadIdx.x;
    if (i < NN * DD / 4) {
        int n = i >> 5;
        float inv = 1.0f / fmaxf((float)g_deg[n], 1.0f);
        float4 v = *(const float4*)&g_agg[i * 4];
        float4 bsv = *(const float4*)&bias[(i & 31) * 4];
        v.x = v.x * inv + bsv.x;
        v.y = v.y * inv + bsv.y;
        v.z = v.z * inv + bsv.z;
        v.w = v.w * inv + bsv.w;
        if (do_relu) {
            v.x = fmaxf(v.x, 0.f); v.y = fmaxf(v.y, 0.f);
            v.z = fmaxf(v.z, 0.f); v.w = fmaxf(v.w, 0.f);
        }
        *(float4*)&g_x[i * 4] = v;
        *(float4*)&g_agg[i * 4] = make_float4(0.f, 0.f, 0.f, 0.f);
    }
}

// ---------------- decode ----------------
__global__ void k_zero_acc() {
    int i = threadIdx.x;
    if (i < 3) g_acc[i] = 0.0;
}

__device__ __forceinline__ float softplusf(float x) {
    return fmaxf(x, 0.f) + log1pf(expf(-fabsf(x)));
}

__global__ __launch_bounds__(256) void k_decode(const int* __restrict__ hh,
                                                const int* __restrict__ tt,
                                                const int* __restrict__ et,
                                                const int* __restrict__ ng,
                                                const float* __restrict__ rel,
                                                float* __restrict__ out) {
    __shared__ float s_lp[8], s_ln[8], s_au[8];
    int w = (blockIdx.x * blockDim.x + threadIdx.x) >> 5;
    int lane = threadIdx.x & 31;
    int wid = threadIdx.x >> 5;
    float lp = 0.f, ln = 0.f, au = 0.f;
    if (w < EE) {
        int a = hh[w], b = tt[w], c = ng[w], r = et[w];
        float4 xh = *(const float4*)&g_x[a * DD + lane * 4];
        float4 xt = *(const float4*)&g_x[b * DD + lane * 4];
        float4 xn = *(const float4*)&g_x[c * DD + lane * 4];
        float4 re = *(const float4*)&rel[r * DD + lane * 4];
        float hx = xh.x * re.x, hy = xh.y * re.y, hz = xh.z * re.z, hw = xh.w * re.w;
        float p = hx * xt.x + hy * xt.y + hz * xt.z + hw * xt.w;
        float q = hx * xn.x + hy * xn.y + hz * xn.z + hw * xn.w;
#pragma unroll
        for (int o = 16; o; o >>= 1) {
            p += __shfl_xor_sync(0xFFFFFFFFu, p, o);
            q += __shfl_xor_sync(0xFFFFFFFFu, q, o);
        }
        if (lane == 0) {
            out[w] = p;
            lp = softplusf(-p);
            ln = softplusf(q);
            au = (p > q) ? 1.f : 0.f;
        }
    }
    if (lane == 0) { s_lp[wid] = lp; s_ln[wid] = ln; s_au[wid] = au; }
    __syncthreads();
    if (threadIdx.x == 0) {
        double A = 0, Bd = 0, C = 0;
#pragma unroll
        for (int k = 0; k < 8; k++) { A += s_lp[k]; Bd += s_ln[k]; C += s_au[k]; }
        atomicAdd(&g_acc[0], A);
        atomicAdd(&g_acc[1], Bd);
        atomicAdd(&g_acc[2], C);
    }
}

__global__ void k_final(float* __restrict__ out, int out_size) {
    if (blockIdx.x == 0 && threadIdx.x == 0) {
        double inv = 1.0 / (double)EE;
        if (out_size >= EE + 1) out[EE] = (float)(0.5 * (g_acc[0] + g_acc[1]) * inv);
        if (out_size >= EE + 2) out[EE + 1] = (float)(g_acc[2] * inv);
    }
}

// ---------------- launch ----------------
extern "C" void kernel_launch(void* const* d_in, const int* in_sizes, int n_in,
                              void* d_out, int out_size) {
    const float* emb    = (const float*)d_in[0];
    const float* ebias  = (const float*)d_in[1];
    const float* bases1 = (const float*)d_in[2];
    const float* comp1  = (const float*)d_in[3];
    const float* bias1  = (const float*)d_in[4];
    const float* bases2 = (const float*)d_in[5];
    const float* comp2  = (const float*)d_in[6];
    const float* bias2  = (const float*)d_in[7];
    const float* rel    = (const float*)d_in[8];
    const int*   eidx   = (const int*)d_in[9];
    const int*   etype  = (const int*)d_in[10];
    const int*   negt   = (const int*)d_in[11];
    const int* src = eidx;
    const int* dst = eidx + EE;
    float* out = (float*)d_out;

    // CSR build (dst-sorted edge arrays) + W transposes + x0
    k_zero_deg<<<(NN + 255) / 256, 256>>>();
    k_count_deg<<<(EE + 255) / 256, 256>>>(dst);
    k_scan<<<1, SCAN_T>>>();
    k_fill<<<(EE + 255) / 256, 256>>>(src, dst, etype);
    k_wt<<<(BB * DD * DD + 255) / 256, 256>>>(bases1, 0);
    k_wt<<<(BB * DD * DD + 255) / 256, 256>>>(bases2, 1);
    k_x0<<<(NN * DD / 4 + 255) / 256, 256>>>(emb, ebias);

    dim3 ggrid(BB, (NN + 127) / 128);   // (4, 391)
    int sc_blocks = EE / 4 / 8;         // warp = 4 edges, 8 warps/block -> 10000 blocks

    // ---- layer 1 ----
    k_gemm_mma<<<ggrid, 256>>>(0);
    k_scatter<<<sc_blocks, 256>>>(comp1);
    k_finish<<<(NN * DD / 4 + 255) / 256, 256>>>(bias1, 1);

    // ---- layer 2 ----
    k_gemm_mma<<<ggrid, 256>>>(1);
    k_scatter<<<sc_blocks, 256>>>(comp2);
    k_finish<<<(NN * DD / 4 + 255) / 256, 256>>>(bias2, 0);

    // ---- decode ----
    k_zero_acc<<<1, 32>>>();
    k_decode<<<EE / 8, 256>>>(src, dst, etype, negt, rel, out);
    k_final<<<1, 32>>>(out, out_size);
}

// round 17
// speedup vs baseline: 1.0809x; 1.0600x over previous
#include <cuda_runtime.h>
#include <cuda_fp16.h>
#include <math.h>

#define NN 50000        // num nodes
#define DD 128          // embedding dim
#define BB 4            // num bases
#define EE 320000       // num edges
#define RR 12           // num relations
#define NB 313          // ceil(EE/1024) histogram blocks
#define MAXT 2512       // max 128-edge tiles (EE/128 + RR)
#define MAXP (MAXT*128) // padded edge slots

#define XSTRIDE 68      // half2 cells per row (64 + pad4 -> conflict-free)
#define MSTRIDE 132     // fp32 msg stride
#define FUSED_SMEM (1024 + 2*128*XSTRIDE*4)   // 70656 B

// ---------------- static scratch ----------------
__device__ float  g_x[NN * DD];          // node features, 25.6 MB
__device__ float  g_agg[NN * DD];        // scatter accumulator, 25.6 MB
__device__ __half g_Wc[2 * RR * DD * DD];// combined per-relation W, fp16 [l][r][n][k]
__device__ int    g_deg[NN];
__device__ int    g_bh[RR * NB];         // per-block type histogram
__device__ int    g_bh2[RR * NB];        // exclusive prefix per (r, block)
__device__ int    g_tcnt[RR];
__device__ int    g_poff[RR + 1];        // padded relation offsets
__device__ int    g_tile_r[MAXT];
__device__ int    g_pssrc[MAXP];         // src, type-sorted + padded
__device__ int    g_psdst[MAXP];         // dst, type-sorted + padded (-1 = pad)
__device__ double g_acc[3];

// ---------------- degree ----------------
__global__ void k_zero_deg() {
    int i = blockIdx.x * blockDim.x + threadIdx.x;
    if (i < NN) g_deg[i] = 0;
}
__global__ void k_count_deg(const int* __restrict__ dst) {
    int e = blockIdx.x * blockDim.x + threadIdx.x;
    if (e < EE) atomicAdd(&g_deg[dst[e]], 1);
}

// ---------------- per-block relation histogram ----------------
__global__ __launch_bounds__(256) void k_hist(const int* __restrict__ et) {
    __shared__ int h[RR];
    int b = blockIdx.x, tid = threadIdx.x;
    if (tid < RR) h[tid] = 0;
    __syncthreads();
#pragma unroll
    for (int j = 0; j < 4; j++) {
        int e = b * 1024 + j * 256 + tid;
        if (e < EE) atomicAdd(&h[et[e]], 1);
    }
    __syncthreads();
    if (tid < RR) g_bh[tid * NB + b] = h[tid];
}

// ---------------- scan histogram: per-relation exclusive prefix over blocks ----------------
__global__ __launch_bounds__(384) void k_scanhist() {
    int lane = threadIdx.x & 31;
    int r = threadIdx.x >> 5;
    if (r >= RR) return;
    int running = 0;
    for (int c = 0; c < 10; c++) {
        int idx = c * 32 + lane;
        int v0 = (idx < NB) ? g_bh[r * NB + idx] : 0;
        int v = v0;
#pragma unroll
        for (int off = 1; off < 32; off <<= 1) {
            int n = __shfl_up_sync(0xFFFFFFFFu, v, off);
            if (lane >= off) v += n;
        }
        if (idx < NB) g_bh2[r * NB + idx] = running + v - v0;
        running += __shfl_sync(0xFFFFFFFFu, v, 31);
    }
    if (lane == 0) g_tcnt[r] = running;
}

// ---------------- padded relation offsets (1 thread, 12 iters) ----------------
__global__ void k_ttab_a() {
    if (threadIdx.x == 0) {
        int poff = 0;
        for (int r = 0; r < RR; r++) {
            g_poff[r] = poff;
            int nt = (g_tcnt[r] + 127) >> 7;
            poff += nt << 7;
        }
        g_poff[RR] = poff;
    }
}

// ---------------- tile table + pad slots ----------------
__global__ __launch_bounds__(256) void k_ttab_b() {
    int p = blockIdx.x * blockDim.x + threadIdx.x;
    if (p >= MAXP) return;
    int p12 = g_poff[RR];
    if (p < p12) {
        int r = 0;
        while (p >= g_poff[r + 1]) r++;
        if ((p & 127) == 0) g_tile_r[p >> 7] = r;
        int local = p - g_poff[r];
        if (local >= g_tcnt[r]) { g_pssrc[p] = 0; g_psdst[p] = -1; }
    } else {
        if ((p & 127) == 0) g_tile_r[p >> 7] = 0;
        g_pssrc[p] = 0;
        g_psdst[p] = -1;
    }
}

// ---------------- place edges into type-sorted slots ----------------
__global__ __launch_bounds__(256) void k_place(const int* __restrict__ src,
                                               const int* __restrict__ dst,
                                               const int* __restrict__ et) {
    __shared__ int cur[RR];
    int b = blockIdx.x, tid = threadIdx.x;
    if (tid < RR) cur[tid] = g_poff[tid] + g_bh2[tid * NB + b];
    __syncthreads();
#pragma unroll
    for (int j = 0; j < 4; j++) {
        int e = b * 1024 + j * 256 + tid;
        if (e < EE) {
            int t = et[e];
            int pos = atomicAdd(&cur[t], 1);
            g_pssrc[pos] = src[e];
            g_psdst[pos] = dst[e];
        }
    }
}

// ---------------- combined per-relation weights: W_r = sum_b comp[r,b]*bases[b], fp16 [n][k] ----------------
__global__ __launch_bounds__(256) void k_wc(const float* __restrict__ bases1,
                                            const float* __restrict__ comp1,
                                            const float* __restrict__ bases2,
                                            const float* __restrict__ comp2) {
    int i = blockIdx.x * blockDim.x + threadIdx.x;
    if (i >= 2 * RR * DD * DD) return;
    int k = i & 127;
    int n = (i >> 7) & 127;
    int lr = i >> 14;              // l*RR + r, 0..23
    int l = lr / RR, r = lr % RR;
    const float* comp = l ? comp2 : comp1;
    const float* bas  = l ? bases2 : bases1;
    float v = 0.f;
#pragma unroll
    for (int b = 0; b < BB; b++)
        v += comp[r * BB + b] * bas[b * DD * DD + k * DD + n];
    g_Wc[i] = __float2half(v);
}

// ---------------- x0 = relu(emb + bias), zero agg (float4) ----------------
__global__ void k_x0(const float* __restrict__ emb, const float* __restrict__ eb) {
    int i = blockIdx.x * blockDim.x + threadIdx.x;
    if (i < NN * DD / 4) {
        float4 v = *(const float4*)&emb[i * 4];
        float4 bsv = *(const float4*)&eb[(i & 31) * 4];
        v.x = fmaxf(v.x + bsv.x, 0.f);
        v.y = fmaxf(v.y + bsv.y, 0.f);
        v.z = fmaxf(v.z + bsv.z, 0.f);
        v.w = fmaxf(v.w + bsv.w, 0.f);
        *(float4*)&g_x[i * 4] = v;
        *(float4*)&g_agg[i * 4] = make_float4(0.f, 0.f, 0.f, 0.f);
    }
}

// ---------------- helpers ----------------
__device__ __forceinline__ void mma_f16(float c[4], const unsigned a[4], const unsigned b[2]) {
    asm volatile(
        "mma.sync.aligned.m16n8k16.row.col.f32.f16.f16.f32 "
        "{%0,%1,%2,%3}, {%4,%5,%6,%7}, {%8,%9}, {%0,%1,%2,%3};\n"
        : "+f"(c[0]), "+f"(c[1]), "+f"(c[2]), "+f"(c[3])
        : "r"(a[0]), "r"(a[1]), "r"(a[2]), "r"(a[3]), "r"(b[0]), "r"(b[1]));
}
__device__ __forceinline__ void red4(float* p, float4 v) {
    asm volatile("red.global.add.v4.f32 [%0], {%1,%2,%3,%4};"
                 :: "l"(p), "f"(v.x), "f"(v.y), "f"(v.z), "f"(v.w) : "memory");
}

// ---------------- fused gather-GEMM-scatter: 1 block = 128 edges of one relation ----------------
// msg[128,128] = x[src[0..127]] @ W_r ; red.v4 each row into agg[dst]
__global__ __launch_bounds__(256, 2) void k_fused(int layer) {
    extern __shared__ char sm[];
    int* s_src = (int*)sm;                                        // 128 ints
    int* s_dst = (int*)(sm + 512);                                // 128 ints
    unsigned (*Xh)[XSTRIDE]  = (unsigned(*)[XSTRIDE])(sm + 1024);
    unsigned (*Wst)[XSTRIDE] = (unsigned(*)[XSTRIDE])(sm + 1024 + 128 * XSTRIDE * 4);
    float* msg = (float*)(sm + 1024);                             // reuses Xh/Wst space

    const int tile = blockIdx.x;
    const int tid = threadIdx.x;
    const int lane = tid & 31;
    const int wid = tid >> 5;
    const int wm = wid & 3, wn = wid >> 2;
    const int gid = lane >> 2, tig = lane & 3;
    const int r = g_tile_r[tile];

    if (tid < 128) {
        s_src[tid] = g_pssrc[tile * 128 + tid];
        s_dst[tid] = g_psdst[tile * 128 + tid];
    }
    __syncthreads();

    // ---- gather 128 x-rows (each warp: 16 rows, 512B coalesced per row) ----
#pragma unroll
    for (int j = 0; j < 16; j++) {
        int row = j * 8 + wid;
        int s = s_src[row];
        float4 v = *(const float4*)&g_x[s * DD + lane * 4];
        __half2 h0 = __floats2half2_rn(v.x, v.y);
        __half2 h1 = __floats2half2_rn(v.z, v.w);
        uint2 u;
        u.x = *(const unsigned*)&h0;
        u.y = *(const unsigned*)&h1;
        *(uint2*)&Xh[row][lane * 2] = u;
    }
    // ---- load W_r [n][k] fp16 (vectorized) ----
    {
        const uint4* Wp = (const uint4*)&g_Wc[(layer * RR + r) * DD * DD];
#pragma unroll
        for (int j = 0; j < 8; j++) {
            int idx = j * 256 + tid;
            int n = idx >> 4, q = idx & 15;
            uint4 u = Wp[n * 16 + q];
            *(uint4*)&Wst[n][q * 4] = u;
        }
    }
    __syncthreads();

    // ---- 128x128x128 fp16 MMA ----
    float c[2][8][4];
#pragma unroll
    for (int mt = 0; mt < 2; mt++)
#pragma unroll
        for (int nt = 0; nt < 8; nt++)
#pragma unroll
            for (int i = 0; i < 4; i++) c[mt][nt][i] = 0.f;

#pragma unroll
    for (int ki = 0; ki < 8; ki++) {
        const int o0 = ki * 8 + tig;
        const int o1 = o0 + 4;
        unsigned a[2][4], bf[8][2];
#pragma unroll
        for (int mt = 0; mt < 2; mt++) {
            int mr = wm * 32 + mt * 16 + gid;
            a[mt][0] = Xh[mr][o0];
            a[mt][1] = Xh[mr + 8][o0];
            a[mt][2] = Xh[mr][o1];
            a[mt][3] = Xh[mr + 8][o1];
        }
#pragma unroll
        for (int nt = 0; nt < 8; nt++) {
            int nc = wn * 64 + nt * 8 + gid;
            bf[nt][0] = Wst[nc][o0];
            bf[nt][1] = Wst[nc][o1];
        }
#pragma unroll
        for (int mt = 0; mt < 2; mt++)
#pragma unroll
            for (int nt = 0; nt < 8; nt++)
                mma_f16(c[mt][nt], a[mt], bf[nt]);
    }
    __syncthreads();   // all Xh/Wst reads complete before msg overwrite

    // ---- stage msg through smem ----
#pragma unroll
    for (int mt = 0; mt < 2; mt++) {
        int row0 = wm * 32 + mt * 16 + gid;
        int row1 = row0 + 8;
#pragma unroll
        for (int nt = 0; nt < 8; nt++) {
            int col = wn * 64 + nt * 8 + 2 * tig;
            *(float2*)&msg[row0 * MSTRIDE + col] = make_float2(c[mt][nt][0], c[mt][nt][1]);
            *(float2*)&msg[row1 * MSTRIDE + col] = make_float2(c[mt][nt][2], c[mt][nt][3]);
        }
    }
    __syncthreads();

    // ---- red.v4 each row to agg[dst] (warp per row, 16 rows/warp) ----
#pragma unroll
    for (int j = 0; j < 16; j++) {
        int row = wid * 16 + j;
        int d = s_dst[row];
        if (d >= 0) {
            float4 v = *(const float4*)&msg[row * MSTRIDE + lane * 4];
            red4(&g_agg[d * DD + lane * 4], v);
        }
    }
}

// ---------------- x = [relu](agg / deg + bias), reset agg ----------------
__global__ void k_finish(const float* __restrict__ bias, int do_relu) {
    int i = blockIdx.x * blockDim.x + threadIdx.x;
    if (i < NN * DD / 4) {
        int n = i >> 5;
        float inv = 1.0f / fmaxf((float)g_deg[n], 1.0f);
        float4 v = *(const float4*)&g_agg[i * 4];
        float4 bsv = *(const float4*)&bias[(i & 31) * 4];
        v.x = v.x * inv + bsv.x;
        v.y = v.y * inv + bsv.y;
        v.z = v.z * inv + bsv.z;
        v.w = v.w * inv + bsv.w;
        if (do_relu) {
            v.x = fmaxf(v.x, 0.f); v.y = fmaxf(v.y, 0.f);
            v.z = fmaxf(v.z, 0.f); v.w = fmaxf(v.w, 0.f);
        }
        *(float4*)&g_x[i * 4] = v;
        *(float4*)&g_agg[i * 4] = make_float4(0.f, 0.f, 0.f, 0.f);
    }
}

// ---------------- decode ----------------
__global__ void k_zero_acc() {
    int i = threadIdx.x;
    if (i < 3) g_acc[i] = 0.0;
}

__device__ __forceinline__ float softplusf(float x) {
    return fmaxf(x, 0.f) + log1pf(expf(-fabsf(x)));
}

__global__ __launch_bounds__(256) void k_decode(const int* __restrict__ hh,
                                                const int* __restrict__ tt,
                                                const int* __restrict__ et,
                                                const int* __restrict__ ng,
                                                const float* __restrict__ rel,
                                                float* __restrict__ out) {
    __shared__ float s_lp[8], s_ln[8], s_au[8];
    int w = (blockIdx.x * blockDim.x + threadIdx.x) >> 5;
    int lane = threadIdx.x & 31;
    int wid = threadIdx.x >> 5;
    float lp = 0.f, ln = 0.f, au = 0.f;
    if (w < EE) {
        int a = hh[w], b = tt[w], c = ng[w], r = et[w];
        float4 xh = *(const float4*)&g_x[a * DD + lane * 4];
        float4 xt = *(const float4*)&g_x[b * DD + lane * 4];
        float4 xn = *(const float4*)&g_x[c * DD + lane * 4];
        float4 re = *(const float4*)&rel[r * DD + lane * 4];
        float hx = xh.x * re.x, hy = xh.y * re.y, hz = xh.z * re.z, hw = xh.w * re.w;
        float p = hx * xt.x + hy * xt.y + hz * xt.z + hw * xt.w;
        float q = hx * xn.x + hy * xn.y + hz * xn.z + hw * xn.w;
#pragma unroll
        for (int o = 16; o; o >>= 1) {
            p += __shfl_xor_sync(0xFFFFFFFFu, p, o);
            q += __shfl_xor_sync(0xFFFFFFFFu, q, o);
        }
        if (lane == 0) {
            out[w] = p;
            lp = softplusf(-p);
            ln = softplusf(q);
            au = (p > q) ? 1.f : 0.f;
        }
    }
    if (lane == 0) { s_lp[wid] = lp; s_ln[wid] = ln; s_au[wid] = au; }
    __syncthreads();
    if (threadIdx.x == 0) {
        double A = 0, Bd = 0, C = 0;
#pragma unroll
        for (int k = 0; k < 8; k++) { A += s_lp[k]; Bd += s_ln[k]; C += s_au[k]; }
        atomicAdd(&g_acc[0], A);
        atomicAdd(&g_acc[1], Bd);
        atomicAdd(&g_acc[2], C);
    }
}

__global__ void k_final(float* __restrict__ out, int out_size) {
    if (blockIdx.x == 0 && threadIdx.x == 0) {
        double inv = 1.0 / (double)EE;
        if (out_size >= EE + 1) out[EE] = (float)(0.5 * (g_acc[0] + g_acc[1]) * inv);
        if (out_size >= EE + 2) out[EE + 1] = (float)(g_acc[2] * inv);
    }
}

// ---------------- launch ----------------
extern "C" void kernel_launch(void* const* d_in, const int* in_sizes, int n_in,
                              void* d_out, int out_size) {
    const float* emb    = (const float*)d_in[0];
    const float* ebias  = (const float*)d_in[1];
    const float* bases1 = (const float*)d_in[2];
    const float* comp1  = (const float*)d_in[3];
    const float* bias1  = (const float*)d_in[4];
    const float* bases2 = (const float*)d_in[5];
    const float* comp2  = (const float*)d_in[6];
    const float* bias2  = (const float*)d_in[7];
    const float* rel    = (const float*)d_in[8];
    const int*   eidx   = (const int*)d_in[9];
    const int*   etype  = (const int*)d_in[10];
    const int*   negt   = (const int*)d_in[11];
    const int* src = eidx;
    const int* dst = eidx + EE;
    float* out = (float*)d_out;

    static int smem_set = 0;
    if (!smem_set) {
        cudaFuncSetAttribute(k_fused, cudaFuncAttributeMaxDynamicSharedMemorySize, FUSED_SMEM);
        smem_set = 1;
    }

    // preamble: degree, type-sort, combined weights, x0
    k_zero_deg<<<(NN + 255) / 256, 256>>>();
    k_count_deg<<<(EE + 255) / 256, 256>>>(dst);
    k_hist<<<NB, 256>>>(etype);
    k_scanhist<<<1, 384>>>();
    k_ttab_a<<<1, 32>>>();
    k_ttab_b<<<MAXP / 256, 256>>>();
    k_place<<<NB, 256>>>(src, dst, etype);
    k_wc<<<(2 * RR * DD * DD + 255) / 256, 256>>>(bases1, comp1, bases2, comp2);
    k_x0<<<(NN * DD / 4 + 255) / 256, 256>>>(emb, ebias);

    // ---- layer 1 ----
    k_fused<<<MAXT, 256, FUSED_SMEM>>>(0);
    k_finish<<<(NN * DD / 4 + 255) / 256, 256>>>(bias1, 1);

    // ---- layer 2 ----
    k_fused<<<MAXT, 256, FUSED_SMEM>>>(1);
    k_finish<<<(NN * DD / 4 + 255) / 256, 256>>>(bias2, 0);

    // ---- decode ----
    k_zero_acc<<<1, 32>>>();
    k_decode<<<EE / 8, 256>>>(src, dst, etype, negt, rel, out);
    k_final<<<1, 32>>>(out, out_size);
}